// round 12
// baseline (speedup 1.0000x reference)
#include <cuda_runtime.h>
#include <cstdint>
#include <math.h>

#define SEQ 512
#define BATCH 128
#define INDIM 256
#define HIDDIM 512
#define OUTDIM 256
#define K0 768
#define K1 1024
#define NBLK 128
#define NTHR 512

#define SM_W0   0
#define SM_W1   (SM_W0 + K0*4*16)            /* 49152  */
#define SM_RED  (SM_W1 + K1*4*16)            /* 114688; 8*512*16 = 64KB */
#define SM_OACC (SM_RED + 8*512*16)          /* 180224 */
#define SM_WOUT (SM_OACC + 4*64*16)          /* 184320 */
#define SM_BS   (SM_WOUT + 1024*8)           /* 192512 */
#define SMEM_BYTES (SM_BS + 128)             /* 192640 */

__device__ float g_xT[(size_t)SEQ*INDIM*BATCH];   /* [t][k][b] */
__device__ float g_h0[2][HIDDIM*BATCH];           /* [phase][j][b] */
__device__ float g_h1[2][HIDDIM*BATCH];
__device__ unsigned g_cnt;
__device__ unsigned g_gen;

typedef unsigned long long ull;

__device__ __forceinline__ ull PK(float x, float y){
    ull r; asm("mov.b64 %0, {%1, %2};" : "=l"(r) : "f"(x), "f"(y)); return r;
}
__device__ __forceinline__ float2 UPK(ull a){
    float2 f; asm("mov.b64 {%0, %1}, %2;" : "=f"(f.x), "=f"(f.y) : "l"(a)); return f;
}
#define FMA2(acc,a,w) asm("fma.rn.f32x2 %0, %1, %2, %0;" : "+l"(acc) : "l"(a), "l"(w))
#define ADD2(acc,b)   asm("add.rn.f32x2 %0, %0, %1;"     : "+l"(acc) : "l"(b))

__device__ __forceinline__ float sigf(float x){ return 1.0f/(1.0f+expf(-x)); }

__device__ __forceinline__ void grid_sync(){
    __syncthreads();
    if (threadIdx.x == 0){
        volatile unsigned* vg = &g_gen;
        unsigned gen = *vg;
        __threadfence();
        if (atomicAdd(&g_cnt, 1u) == NBLK-1u){
            atomicExch(&g_cnt, 0u);
            __threadfence();
            atomicAdd(&g_gen, 1u);
        } else {
            while (*vg == gen) { __nanosleep(20); }
        }
        __threadfence();
    }
    __syncthreads();
}

/* x [t][b][k] -> g_xT [t][k][b] */
__global__ void transpose_x(const float* __restrict__ x){
    __shared__ float tile[32][33];
    int t = blockIdx.x, k0 = blockIdx.y*32, b0 = blockIdx.z*32;
    const float* src = x + (size_t)t*BATCH*INDIM;
    #pragma unroll
    for (int i = threadIdx.y; i < 32; i += 8)
        tile[i][threadIdx.x] = src[(size_t)(b0+i)*INDIM + k0 + threadIdx.x];
    __syncthreads();
    float* dst = g_xT + (size_t)t*INDIM*BATCH;
    #pragma unroll
    for (int i = threadIdx.y; i < 32; i += 8)
        dst[(size_t)(k0+i)*BATCH + b0 + threadIdx.x] = tile[threadIdx.x][i];
}

__device__ __forceinline__ void load8(float2 v[8], const float* src){
    #pragma unroll
    for (int i = 0; i < 8; i++)
        v[i] = __ldcg((const float2*)(src + i*BATCH));
}

__device__ __forceinline__ void comp8(const float2 v[8], const ulonglong2* wp,
                                      ull* A, ull* B, ull* C, ull* D){
    #pragma unroll
    for (int kk = 0; kk < 8; kk++){
        ull a0 = PK(v[kk].x, v[kk].x), a1 = PK(v[kk].y, v[kk].y);
        #pragma unroll
        for (int u = 0; u < 4; u++){
            ulonglong2 w = wp[kk*4 + u];
            FMA2(A[u], a0, w.x); FMA2(B[u], a0, w.y);
            FMA2(C[u], a1, w.x); FMA2(D[u], a1, w.y);
        }
    }
}

__device__ __forceinline__ void comp8o(const float2 v[8], const ulonglong2* wp,
                                       ull* A, ull* B, ull* C, ull* D,
                                       ull& o0, ull& o1, const ull* w0, const ull* w1){
    #pragma unroll
    for (int kk = 0; kk < 8; kk++){
        ull a0 = PK(v[kk].x, v[kk].x), a1 = PK(v[kk].y, v[kk].y);
        #pragma unroll
        for (int u = 0; u < 4; u++){
            ulonglong2 w = wp[kk*4 + u];
            FMA2(A[u], a0, w.x); FMA2(B[u], a0, w.y);
            FMA2(C[u], a1, w.x); FMA2(D[u], a1, w.y);
        }
        ull vp = PK(v[kk].x, v[kk].y);
        FMA2(o0, vp, w0[kk]); FMA2(o1, vp, w1[kk]);
    }
}

/* n rows (multiple of 8, may be 0) streamed from src with ping-pong reg chunks */
__device__ __forceinline__ void seg(const float* src, int n, const ulonglong2* wp,
                                    ull* A, ull* B, ull* C, ull* D){
    int nc = n >> 3;
    if (nc <= 0) return;
    float2 va[8], vb[8];
    load8(va, src);
    for (int c = 0; c < nc; c += 2){
        if (c+1 < nc) load8(vb, src + (c+1)*8*BATCH);
        comp8(va, wp + c*32, A, B, C, D);
        if (c+1 >= nc) break;
        if (c+2 < nc) load8(va, src + (c+2)*8*BATCH);
        comp8(vb, wp + (c+1)*32, A, B, C, D);
    }
}

__global__ void __launch_bounds__(NTHR, 1) lstm_persist(
    const float* __restrict__ Wg0, const float* __restrict__ bg0,
    const float* __restrict__ Wg1, const float* __restrict__ bg1,
    const float* __restrict__ W_out, const float* __restrict__ b_out,
    float* __restrict__ out)
{
    extern __shared__ char smem[];
    ulonglong2* wS0  = (ulonglong2*)(smem + SM_W0);   /* [k*4+u] = {(wf,wi),(wc,wo)} */
    ulonglong2* wS1  = (ulonglong2*)(smem + SM_W1);
    ulonglong2* redS = (ulonglong2*)(smem + SM_RED);  /* [g*512 + u*128 + b] = (fi, co) */
    ulonglong2* oaccS= (ulonglong2*)(smem + SM_OACC); /* [(g-4)*64+p] = (o0,o1) */
    ull*        wOutS= (ull*)(smem + SM_WOUT);        /* [c*512+j] = (w,w) dup */
    ulonglong2* bS   = (ulonglong2*)(smem + SM_BS);   /* [layer*4+u] = (bfi,bco) */

    const int tid = threadIdx.x, bid = blockIdx.x;
    const int g   = tid >> 6;           /* K-group 0..7 */
    const int p   = tid & 63;           /* batch pair: 2p, 2p+1 */
    const int uo  = tid >> 7;           /* owner unit 0..3 */
    const int bo  = tid & 127;          /* owner batch */

    /* ---- weights / consts -> smem ---- */
    for (int idx = tid; idx < K0*4; idx += NTHR){
        int k = idx >> 2, uu = bid*4 + (idx & 3);
        float wf = Wg0[(size_t)(0*HIDDIM+uu)*K0 + k];
        float wi = Wg0[(size_t)(1*HIDDIM+uu)*K0 + k];
        float wc = Wg0[(size_t)(2*HIDDIM+uu)*K0 + k];
        float wo = Wg0[(size_t)(3*HIDDIM+uu)*K0 + k];
        wS0[idx] = make_ulonglong2(PK(wf,wi), PK(wc,wo));
    }
    for (int idx = tid; idx < K1*4; idx += NTHR){
        int k = idx >> 2, uu = bid*4 + (idx & 3);
        float wf = Wg1[(size_t)(0*HIDDIM+uu)*K1 + k];
        float wi = Wg1[(size_t)(1*HIDDIM+uu)*K1 + k];
        float wc = Wg1[(size_t)(2*HIDDIM+uu)*K1 + k];
        float wo = Wg1[(size_t)(3*HIDDIM+uu)*K1 + k];
        wS1[idx] = make_ulonglong2(PK(wf,wi), PK(wc,wo));
    }
    for (int idx = tid; idx < 2*HIDDIM; idx += NTHR){
        int c = idx >> 9, j = idx & 511;
        float w = W_out[(size_t)(bid*2+c)*HIDDIM + j];
        wOutS[idx] = PK(w, w);
    }
    if (tid < 8){
        int L = tid >> 2, u = tid & 3, ug = bid*4 + u;
        const float* bg = L ? bg1 : bg0;
        bS[tid] = make_ulonglong2(PK(bg[ug], bg[HIDDIM+ug]),
                                  PK(bg[2*HIDDIM+ug], bg[3*HIDDIM+ug]));
    }
    if (g == 0){
        float2 z = make_float2(0.f, 0.f);
        #pragma unroll
        for (int u = 0; u < 4; u++){
            int o2 = (bid*4+u)*BATCH + 2*p;
            *(float2*)(g_h0[0]+o2) = z; *(float2*)(g_h0[1]+o2) = z;
            *(float2*)(g_h1[0]+o2) = z; *(float2*)(g_h1[1]+o2) = z;
        }
    }
    float C0own = 0.f, C1own = 0.f, h0own = 0.f, h1own = 0.f;

    grid_sync();

    const size_t OB = (size_t)SEQ*BATCH*OUTDIM;

    for (int t = 0; t < SEQ; t++){
        const int cw = t & 1, pv = cw ^ 1;

        /* ================= layer 0 (K split 8 ways, direct LDG) ================= */
        const float* xb  = g_xT + (size_t)t*INDIM*BATCH;
        const float* h0p = g_h0[pv];
        ull A[4]={0,0,0,0}, B[4]={0,0,0,0}, C[4]={0,0,0,0}, D[4]={0,0,0,0};

        {
            int base = g*96;
            int nx = 256 - base;
            if (nx < 0) nx = 0; if (nx > 96) nx = 96;
            const ulonglong2* wp = wS0 + base*4;
            const float* srcx = xb + (size_t)base*BATCH + 2*p;
            seg(srcx, nx, wp, A, B, C, D);
            const float* srch = h0p + (size_t)(base + nx - 256)*BATCH + 2*p;
            seg(srch, 96 - nx, wp + nx*4, A, B, C, D);
        }
        __syncthreads();
        {
            int rb = g*512 + 2*p;
            #pragma unroll
            for (int u = 0; u < 4; u++){
                redS[rb + u*128]     = make_ulonglong2(A[u], B[u]);
                redS[rb + u*128 + 1] = make_ulonglong2(C[u], D[u]);
            }
        }
        __syncthreads();
        {
            ull fi = 0, co = 0;
            int slot = uo*128 + bo;
            #pragma unroll
            for (int gg = 0; gg < 8; gg++){
                ulonglong2 r = redS[gg*512 + slot];
                ADD2(fi, r.x); ADD2(co, r.y);
            }
            ulonglong2 bb = bS[uo];
            ADD2(fi, bb.x); ADD2(co, bb.y);
            float2 q1 = UPK(fi), q2 = UPK(co);
            C0own = sigf(q1.x)*C0own + sigf(q1.y)*tanhf(q2.x);
            h0own = sigf(q2.y)*tanhf(C0own);
            g_h0[cw][(bid*4+uo)*BATCH + bo] = h0own;
        }

        grid_sync();   /* the single per-step grid barrier */

        /* ========= layer 1 (K split 8 ways, direct LDG) + fused out[t-1] ========= */
        const float* h0c = g_h0[cw];
        const float* h1p = g_h1[pv];
        #pragma unroll
        for (int u = 0; u < 4; u++){ A[u]=0; B[u]=0; C[u]=0; D[u]=0; }
        ull o0 = 0, o1 = 0;

        {
            const float* src1 = ((g < 4) ? h0c + (size_t)(g*128)*BATCH
                                         : h1p + (size_t)((g-4)*128)*BATCH) + 2*p;
            const ulonglong2* wp = wS1 + (g*128)*4;
            const ull* w0 = wOutS + (g-4)*128;         /* valid only when g>=4 */
            const ull* w1 = wOutS + 512 + (g-4)*128;
            bool fuse = (g >= 4) && (t > 0);
            float2 va[8], vb[8];
            load8(va, src1);
            for (int c = 0; c < 16; c += 2){
                load8(vb, src1 + (c+1)*8*BATCH);
                if (fuse) comp8o(va, wp + c*32, A,B,C,D, o0,o1, w0 + c*8, w1 + c*8);
                else      comp8 (va, wp + c*32, A,B,C,D);
                if (c+2 < 16) load8(va, src1 + (c+2)*8*BATCH);
                if (fuse) comp8o(vb, wp + (c+1)*32, A,B,C,D, o0,o1, w0 + (c+1)*8, w1 + (c+1)*8);
                else      comp8 (vb, wp + (c+1)*32, A,B,C,D);
            }
        }
        __syncthreads();
        {
            int rb = g*512 + 2*p;
            #pragma unroll
            for (int u = 0; u < 4; u++){
                redS[rb + u*128]     = make_ulonglong2(A[u], B[u]);
                redS[rb + u*128 + 1] = make_ulonglong2(C[u], D[u]);
            }
            if (g >= 4 && t > 0) oaccS[(g-4)*64 + p] = make_ulonglong2(o0, o1);
        }
        __syncthreads();
        {
            ull fi = 0, co = 0;
            int slot = uo*128 + bo;
            #pragma unroll
            for (int gg = 0; gg < 8; gg++){
                ulonglong2 r = redS[gg*512 + slot];
                ADD2(fi, r.x); ADD2(co, r.y);
            }
            ulonglong2 bb = bS[4+uo];
            ADD2(fi, bb.x); ADD2(co, bb.y);
            float2 q1 = UPK(fi), q2 = UPK(co);
            C1own = sigf(q1.x)*C1own + sigf(q1.y)*tanhf(q2.x);
            h1own = sigf(q2.y)*tanhf(C1own);
            g_h1[cw][(bid*4+uo)*BATCH + bo] = h1own;
        }
        if (g == 1 && t > 0){
            ulonglong2 q = oaccS[p];
            ull s0 = q.x, s1 = q.y;
            #pragma unroll
            for (int s = 1; s < 4; s++){
                q = oaccS[s*64 + p];
                ADD2(s0, q.x); ADD2(s1, q.y);
            }
            float2 r0 = UPK(s0), r1 = UPK(s1);
            float bo0 = b_out[bid*2], bo1 = b_out[bid*2+1];
            size_t ob = ((size_t)(t-1)*BATCH + 2*p)*OUTDIM + bid*2;
            *(float2*)(out + ob)          = make_float2(r0.x + bo0, r1.x + bo1);
            *(float2*)(out + ob + OUTDIM) = make_float2(r0.y + bo0, r1.y + bo1);
        }
        __syncthreads();   /* protect redS before next step's stores */
    }

    grid_sync();
    /* out[SEQ-1] */
    if (tid < 128){
        int c = tid >> 6, pp = tid & 63;
        ull o = 0;
        const float* h1f = g_h1[(SEQ-1)&1];
        #pragma unroll 4
        for (int j = 0; j < HIDDIM; j++){
            float2 v = __ldcg((const float2*)(h1f + j*BATCH + 2*pp));
            FMA2(o, PK(v.x, v.y), wOutS[c*HIDDIM + j]);
        }
        float2 r = UPK(o);
        float bo2 = b_out[bid*2 + c];
        size_t ob = ((size_t)(SEQ-1)*BATCH + 2*pp)*OUTDIM + bid*2 + c;
        out[ob]          = r.x + bo2;
        out[ob + OUTDIM] = r.y + bo2;
    }
    /* final states: [B][HID] each, order h_0, C_0, h_1, C_1 (owner threads) */
    {
        size_t r = (size_t)bo*HIDDIM + bid*4 + uo;
        out[OB          + r] = h0own;
        out[OB +  65536 + r] = C0own;
        out[OB + 131072 + r] = h1own;
        out[OB + 196608 + r] = C1own;
    }
}

extern "C" void kernel_launch(void* const* d_in, const int* in_sizes, int n_in,
                              void* d_out, int out_size)
{
    (void)in_sizes; (void)n_in; (void)out_size;
    const float* x     = (const float*)d_in[0];
    const float* Wg0   = (const float*)d_in[1];
    const float* bg0   = (const float*)d_in[2];
    const float* Wg1   = (const float*)d_in[3];
    const float* bg1   = (const float*)d_in[4];
    const float* W_out = (const float*)d_in[5];
    const float* b_out = (const float*)d_in[6];

    cudaFuncSetAttribute(lstm_persist,
                         cudaFuncAttributeMaxDynamicSharedMemorySize, SMEM_BYTES);

    transpose_x<<<dim3(SEQ, INDIM/32, BATCH/32), dim3(32, 8)>>>(x);
    lstm_persist<<<NBLK, NTHR, SMEM_BYTES>>>(Wg0, bg0, Wg1, bg1, W_out, b_out,
                                             (float*)d_out);
}